// round 3
// baseline (speedup 1.0000x reference)
#include <cuda_runtime.h>
#include <cuda_bf16.h>
#include <cstdint>

// Problem constants
#define B_   8
#define S_   1024
#define DM_  512
#define H_   8
#define DK_  64

static const size_t ROWS_   = (size_t)B_ * S_;          // 8192
static const size_t LN_N_   = ROWS_ * DM_;              // 4,194,304
static const size_t ATTN_N_ = (size_t)B_*H_*S_*S_;      // 67,108,864
static const size_t MASK_N_ = (size_t)B_*S_*S_;         // 8,388,608

// ---------------- device scratch (allocation-free rule: __device__ globals) ----
__device__ float g_Q  [8192*512];
__device__ float g_K  [8192*512];
__device__ float g_V  [8192*512];
__device__ float g_ctx[8192*512];
__device__ float g_pre[8192*512];
__device__ float g_attn_scratch[67108864ull];   // only used if attn not in d_out
__device__ unsigned char g_mask[8*1024*1024];   // normalized mask (1 byte, 0/1)
__device__ int g_mask_is_u8;

// ---------------- mask dtype detection + normalization ------------------------
__global__ void mask_detect_kernel(const unsigned char* __restrict__ m) {
    __shared__ int cnt;
    if (threadIdx.x == 0) cnt = 0;
    __syncthreads();
    int local = 0;
    for (int i = threadIdx.x; i < 65536; i += 256)
        if ((i & 3) && __ldg(&m[i])) local++;
    if (local) atomicAdd(&cnt, local);
    __syncthreads();
    if (threadIdx.x == 0) g_mask_is_u8 = (cnt > 0) ? 1 : 0;
}

__global__ void mask_convert_kernel(const unsigned char* __restrict__ m) {
    const int u8 = g_mask_is_u8;
    size_t i = (size_t)blockIdx.x * blockDim.x + threadIdx.x;
    if (i < MASK_N_) {
        if (u8) g_mask[i] = (__ldg(&m[i]) != 0);
        else    g_mask[i] = (__ldg(&((const int*)m)[i]) != 0);
    }
}

// ---------------- tiled fp32 GEMM: C[M,N] = A[M,K] @ B[K,N] (+ optional resid)
__global__ __launch_bounds__(256, 2)
void sgemm_kernel(const float* __restrict__ A, const float* __restrict__ Bm,
                  const float* __restrict__ R, float* __restrict__ C,
                  int M, int N, int K, int addResid)
{
    __shared__ float As[8][128];   // transposed A tile
    __shared__ float Bs[8][128];
    const int t = threadIdx.x;
    const int brow = blockIdx.y * 128;
    const int bcol = blockIdx.x * 128;
    const int tx = t & 15, ty = t >> 4;
    const int rowBase = ty * 8, colBase = tx * 8;
    const int aRow = t >> 1, aCol = (t & 1) * 4;
    const int bRow = t >> 5, bCol = (t & 31) * 4;

    float acc[8][8];
    #pragma unroll
    for (int i = 0; i < 8; i++)
        #pragma unroll
        for (int j = 0; j < 8; j++) acc[i][j] = 0.f;

    for (int k0 = 0; k0 < K; k0 += 8) {
        float4 av = *(const float4*)&A[(size_t)(brow + aRow) * K + k0 + aCol];
        As[aCol + 0][aRow] = av.x;
        As[aCol + 1][aRow] = av.y;
        As[aCol + 2][aRow] = av.z;
        As[aCol + 3][aRow] = av.w;
        // FIX: block-column offset `bcol` was missing here (Round-2 rel_err 1.25e-2)
        *(float4*)&Bs[bRow][bCol] = *(const float4*)&Bm[(size_t)(k0 + bRow) * N + bcol + bCol];
        __syncthreads();
        #pragma unroll
        for (int kk = 0; kk < 8; kk++) {
            float ar[8], br[8];
            *(float4*)&ar[0] = *(float4*)&As[kk][rowBase];
            *(float4*)&ar[4] = *(float4*)&As[kk][rowBase + 4];
            *(float4*)&br[0] = *(float4*)&Bs[kk][colBase];
            *(float4*)&br[4] = *(float4*)&Bs[kk][colBase + 4];
            #pragma unroll
            for (int i = 0; i < 8; i++)
                #pragma unroll
                for (int j = 0; j < 8; j++)
                    acc[i][j] += ar[i] * br[j];
        }
        __syncthreads();
    }
    #pragma unroll
    for (int i = 0; i < 8; i++) {
        size_t r = (size_t)(brow + rowBase + i);
        #pragma unroll
        for (int j = 0; j < 8; j += 4) {
            size_t c = (size_t)(bcol + colBase + j);
            float4 v = make_float4(acc[i][j], acc[i][j+1], acc[i][j+2], acc[i][j+3]);
            if (addResid) {
                float4 rv = *(const float4*)&R[r * N + c];
                v.x += rv.x; v.y += rv.y; v.z += rv.z; v.w += rv.w;
            }
            *(float4*)&C[r * N + c] = v;
        }
    }
}

// ---------------- fused attention: scores -> mask/scale -> softmax -> attn out -> ctx
// one block = (batch b, head h, 32 query rows). 256 threads.
// dynamic smem: sS[32][1024] + sKV[128][65] + sQ[2048]  = 172544 B
__global__ __launch_bounds__(256)
void attn_kernel(const float* __restrict__ Q, const float* __restrict__ K,
                 const float* __restrict__ V,
                 float* __restrict__ attn, float* __restrict__ ctx)
{
    extern __shared__ float sm[];
    float* sS  = sm;                    // 32*1024
    float* sKV = sm + 32 * 1024;        // 128*65
    float* sQ  = sKV + 128 * 65;        // 2048 floats (reused as reduce buffer)

    const int t = threadIdx.x;
    const int b = blockIdx.z, h = blockIdx.y;
    const int q0 = blockIdx.x * 32;
    const size_t rowbase = (size_t)b * 1024;
    const float* Qb = Q + (rowbase + q0) * 512 + h * 64;
    const float* Kb = K + rowbase * 512 + h * 64;
    const float* Vb = V + rowbase * 512 + h * 64;

    // load Q tile 32x64
    #pragma unroll
    for (int p = 0; p < 2; p++) {
        int idx = p * 256 + t;
        int r = idx >> 4, j = (idx & 15) * 4;
        *(float4*)&sQ[r * 64 + j] = *(const float4*)&Qb[(size_t)r * 512 + j];
    }

    const int rg = t >> 5;   // warp id = row-group (4 rows)
    const int cg = t & 31;   // lane = col group (cols cg + 32u)

    // ---- Phase 1: raw scores into sS ----
    for (int ch = 0; ch < 8; ch++) {
        const int s0 = ch * 128;
        __syncthreads();
        #pragma unroll
        for (int p = 0; p < 8; p++) {
            int idx = p * 256 + t;
            int r = idx >> 4, j = (idx & 15) * 4;
            float4 v = *(const float4*)&Kb[(size_t)(s0 + r) * 512 + j];
            float* d = &sKV[r * 65 + j];
            d[0] = v.x; d[1] = v.y; d[2] = v.z; d[3] = v.w;
        }
        __syncthreads();
        float acc[4][4];
        #pragma unroll
        for (int i = 0; i < 4; i++)
            #pragma unroll
            for (int u = 0; u < 4; u++) acc[i][u] = 0.f;
        #pragma unroll
        for (int k4 = 0; k4 < 64; k4 += 4) {
            float qa[4][4];
            #pragma unroll
            for (int i = 0; i < 4; i++)
                *(float4*)qa[i] = *(const float4*)&sQ[(rg * 4 + i) * 64 + k4];
            #pragma unroll
            for (int kk = 0; kk < 4; kk++) {
                #pragma unroll
                for (int u = 0; u < 4; u++) {
                    float kv = sKV[(cg + 32 * u) * 65 + k4 + kk];
                    #pragma unroll
                    for (int i = 0; i < 4; i++)
                        acc[i][u] += qa[i][kk] * kv;
                }
            }
        }
        #pragma unroll
        for (int i = 0; i < 4; i++)
            #pragma unroll
            for (int u = 0; u < 4; u++)
                sS[(rg * 4 + i) * 1024 + s0 + cg + 32 * u] = acc[i][u];
    }
    __syncthreads();

    // ---- Phase 2: mask + scale + exact softmax; write attn ----
    {
        const int warp = rg, lane = cg;
        const unsigned char* mb = g_mask + ((size_t)b * 1024 + q0) * 1024;
        #pragma unroll
        for (int ri = 0; ri < 4; ri++) {
            int r = warp * 4 + ri;
            float* srow = &sS[r * 1024];
            const uchar4* mrow = (const uchar4*)(mb + (size_t)r * 1024);
            float mx = -3.0e38f;
            #pragma unroll
            for (int j = 0; j < 8; j++) {
                int c4 = lane + j * 32;
                uchar4 mk = mrow[c4];
                float4 sv = *(float4*)&srow[c4 * 4];
                sv.x = mk.x ? -1e9f : sv.x * 0.125f;
                sv.y = mk.y ? -1e9f : sv.y * 0.125f;
                sv.z = mk.z ? -1e9f : sv.z * 0.125f;
                sv.w = mk.w ? -1e9f : sv.w * 0.125f;
                *(float4*)&srow[c4 * 4] = sv;
                mx = fmaxf(mx, fmaxf(fmaxf(sv.x, sv.y), fmaxf(sv.z, sv.w)));
            }
            #pragma unroll
            for (int o = 16; o > 0; o >>= 1)
                mx = fmaxf(mx, __shfl_xor_sync(0xffffffffu, mx, o));
            float l = 0.f;
            #pragma unroll
            for (int j = 0; j < 8; j++) {
                int c4 = lane + j * 32;
                float4 sv = *(float4*)&srow[c4 * 4];
                sv.x = __expf(sv.x - mx);
                sv.y = __expf(sv.y - mx);
                sv.z = __expf(sv.z - mx);
                sv.w = __expf(sv.w - mx);
                *(float4*)&srow[c4 * 4] = sv;
                l += (sv.x + sv.y) + (sv.z + sv.w);
            }
            #pragma unroll
            for (int o = 16; o > 0; o >>= 1)
                l += __shfl_xor_sync(0xffffffffu, l, o);
            float rinv = 1.0f / l;
            float* arow = attn + ((size_t)(b * 8 + h) * 1024 + q0 + r) * 1024;
            #pragma unroll
            for (int j = 0; j < 8; j++) {
                int c4 = lane + j * 32;
                float4 sv = *(float4*)&srow[c4 * 4];
                sv.x *= rinv; sv.y *= rinv; sv.z *= rinv; sv.w *= rinv;
                *(float4*)&srow[c4 * 4] = sv;
                *(float4*)&arow[c4 * 4] = sv;
            }
        }
    }

    // ---- Phase 3: ctx = P @ V (split-k over two 128-thread groups) ----
    const int g   = t >> 7;       // 0 or 1
    const int tg  = t & 127;
    const int rg3 = tg >> 4;      // rows rg3*4 .. +3
    const int cg3 = tg & 15;      // cols cg3 + 16u
    float cacc[4][4];
    #pragma unroll
    for (int i = 0; i < 4; i++)
        #pragma unroll
        for (int u = 0; u < 4; u++) cacc[i][u] = 0.f;

    for (int ch = 0; ch < 8; ch++) {
        const int s0 = ch * 128;
        __syncthreads();
        #pragma unroll
        for (int p = 0; p < 8; p++) {
            int idx = p * 256 + t;
            int r = idx >> 4, j = (idx & 15) * 4;
            float4 v = *(const float4*)&Vb[(size_t)(s0 + r) * 512 + j];
            float* d = &sKV[r * 65 + j];
            d[0] = v.x; d[1] = v.y; d[2] = v.z; d[3] = v.w;
        }
        __syncthreads();
        const int kb = g * 64;
        #pragma unroll
        for (int k4 = 0; k4 < 64; k4 += 4) {
            float pa[4][4];
            #pragma unroll
            for (int i = 0; i < 4; i++)
                *(float4*)pa[i] = *(const float4*)&sS[(rg3 * 4 + i) * 1024 + s0 + kb + k4];
            #pragma unroll
            for (int kk = 0; kk < 4; kk++) {
                #pragma unroll
                for (int u = 0; u < 4; u++) {
                    float vv = sKV[(kb + k4 + kk) * 65 + cg3 + 16 * u];
                    #pragma unroll
                    for (int i = 0; i < 4; i++)
                        cacc[i][u] += pa[i][kk] * vv;
                }
            }
        }
    }
    __syncthreads();
    if (g == 1) {
        #pragma unroll
        for (int i = 0; i < 4; i++)
            #pragma unroll
            for (int u = 0; u < 4; u++)
                sQ[tg * 16 + i * 4 + u] = cacc[i][u];
    }
    __syncthreads();
    if (g == 0) {
        float* cb = ctx + ((size_t)b * 1024 + q0) * 512 + h * 64;
        #pragma unroll
        for (int i = 0; i < 4; i++)
            #pragma unroll
            for (int u = 0; u < 4; u++)
                cb[(size_t)(rg3 * 4 + i) * 512 + cg3 + 16 * u] =
                    cacc[i][u] + sQ[tg * 16 + i * 4 + u];
    }
}

// ---------------- LayerNorm over last dim (512), one row per block -----------
__global__ __launch_bounds__(128)
void ln_kernel(const float* __restrict__ X, const float* __restrict__ gamma,
               const float* __restrict__ beta, float* __restrict__ out)
{
    __shared__ float red[8];
    const int row = blockIdx.x, t = threadIdx.x;
    const float* x = X + (size_t)row * 512;
    float4 v = *(const float4*)&x[t * 4];
    float s  = (v.x + v.y) + (v.z + v.w);
    float s2 = v.x * v.x + v.y * v.y + v.z * v.z + v.w * v.w;
    #pragma unroll
    for (int o = 16; o > 0; o >>= 1) {
        s  += __shfl_xor_sync(0xffffffffu, s,  o);
        s2 += __shfl_xor_sync(0xffffffffu, s2, o);
    }
    const int warp = t >> 5, lane = t & 31;
    if (lane == 0) { red[warp] = s; red[4 + warp] = s2; }
    __syncthreads();
    s  = red[0] + red[1] + red[2] + red[3];
    s2 = red[4] + red[5] + red[6] + red[7];
    float mean = s * (1.0f / 512.0f);
    float var  = s2 * (1.0f / 512.0f) - mean * mean;
    float rstd = rsqrtf(var + 1e-5f);
    float4 gv = *(const float4*)&gamma[t * 4];
    float4 bv = *(const float4*)&beta[t * 4];
    float4 o4;
    o4.x = (v.x - mean) * rstd * gv.x + bv.x;
    o4.y = (v.y - mean) * rstd * gv.y + bv.y;
    o4.z = (v.z - mean) * rstd * gv.z + bv.z;
    o4.w = (v.w - mean) * rstd * gv.w + bv.w;
    *(float4*)&out[(size_t)row * 512 + t * 4] = o4;
}

// ---------------- launch ------------------------------------------------------
extern "C" void kernel_launch(void* const* d_in, const int* in_sizes, int n_in,
                              void* d_out, int out_size)
{
    const float* iQ   = (const float*)d_in[0];
    const float* iK   = (const float*)d_in[1];
    const float* iV   = (const float*)d_in[2];
    const unsigned char* maskRaw = (const unsigned char*)d_in[3];
    const float* WQ   = (const float*)d_in[4];
    const float* WK   = (const float*)d_in[5];
    const float* WV   = (const float*)d_in[6];
    const float* Wfc  = (const float*)d_in[7];
    const float* gam  = (const float*)d_in[8];
    const float* bet  = (const float*)d_in[9];

    float *gq, *gk, *gv, *gctx, *gpre, *gattn;
    cudaGetSymbolAddress((void**)&gq,    g_Q);
    cudaGetSymbolAddress((void**)&gk,    g_K);
    cudaGetSymbolAddress((void**)&gv,    g_V);
    cudaGetSymbolAddress((void**)&gctx,  g_ctx);
    cudaGetSymbolAddress((void**)&gpre,  g_pre);
    cudaGetSymbolAddress((void**)&gattn, g_attn_scratch);

    float* out = (float*)d_out;
    float* out_ln;
    float* out_attn;
    size_t os = (size_t)out_size;
    if (os >= LN_N_ + ATTN_N_)      { out_ln = out;   out_attn = out + LN_N_; }
    else if (os == ATTN_N_)         { out_attn = out; out_ln = gq; /* g_Q free by LN time */ }
    else                            { out_ln = out;   out_attn = gattn; }

    // mask normalization (dtype-robust)
    mask_detect_kernel<<<1, 256>>>(maskRaw);
    mask_convert_kernel<<<(int)((MASK_N_ + 255) / 256), 256>>>(maskRaw);

    // QKV projections
    dim3 gGemm(512 / 128, 8192 / 128);
    sgemm_kernel<<<gGemm, 256>>>(iQ, WQ, nullptr, gq, 8192, 512, 512, 0);
    sgemm_kernel<<<gGemm, 256>>>(iK, WK, nullptr, gk, 8192, 512, 512, 0);
    sgemm_kernel<<<gGemm, 256>>>(iV, WV, nullptr, gv, 8192, 512, 512, 0);

    // fused attention
    const int smemBytes = (32 * 1024 + 128 * 65 + 2048) * 4;  // 172544
    cudaFuncSetAttribute(attn_kernel, cudaFuncAttributeMaxDynamicSharedMemorySize, smemBytes);
    attn_kernel<<<dim3(32, 8, 8), 256, smemBytes>>>(gq, gk, gv, out_attn, gctx);

    // output projection + residual
    sgemm_kernel<<<gGemm, 256>>>(gctx, Wfc, iQ, gpre, 8192, 512, 512, 1);

    // layernorm
    ln_kernel<<<8192, 128>>>(gpre, gam, bet, out_ln);
}

// round 4
// speedup vs baseline: 2.0035x; 2.0035x over previous
#include <cuda_runtime.h>
#include <cuda_bf16.h>
#include <cstdint>

// Problem constants
#define B_   8
#define S_   1024
#define DM_  512
#define H_   8
#define DK_  64
#define SP   1028   // sS row stride (pad vs 1024 to break bank alignment)

static const size_t ROWS_   = (size_t)B_ * S_;          // 8192
static const size_t LN_N_   = ROWS_ * DM_;              // 4,194,304
static const size_t ATTN_N_ = (size_t)B_*H_*S_*S_;      // 67,108,864
static const size_t MASK_N_ = (size_t)B_*S_*S_;         // 8,388,608

// ---------------- device scratch ----------------------------------------------
__device__ float g_Q  [8192*512];
__device__ float g_K  [8192*512];
__device__ float g_V  [8192*512];
__device__ float g_ctx[8192*512];
__device__ float g_pre[8192*512];
__device__ float g_attn_scratch[67108864ull];
__device__ unsigned char g_mask[8*1024*1024];
__device__ int g_mask_is_u8;

// ---------------- tf32 helpers ------------------------------------------------
__device__ __forceinline__ uint32_t f2tf(float f) {
    uint32_t r;
    asm("cvt.rna.tf32.f32 %0, %1;" : "=r"(r) : "f"(f));
    return r;
}

// D += A(16x8) * B(8x8), tf32 inputs, fp32 accum
__device__ __forceinline__ void mma8(float* c, const uint32_t* a, uint32_t b0, uint32_t b1) {
    asm volatile("mma.sync.aligned.m16n8k8.row.col.f32.tf32.tf32.f32 "
        "{%0,%1,%2,%3}, {%4,%5,%6,%7}, {%8,%9}, {%0,%1,%2,%3};"
        : "+f"(c[0]), "+f"(c[1]), "+f"(c[2]), "+f"(c[3])
        : "r"(a[0]), "r"(a[1]), "r"(a[2]), "r"(a[3]), "r"(b0), "r"(b1));
}

// ---------------- mask dtype detection + normalization ------------------------
__global__ void mask_detect_kernel(const unsigned char* __restrict__ m) {
    __shared__ int cnt;
    if (threadIdx.x == 0) cnt = 0;
    __syncthreads();
    int local = 0;
    for (int i = threadIdx.x; i < 65536; i += 256)
        if ((i & 3) && __ldg(&m[i])) local++;
    if (local) atomicAdd(&cnt, local);
    __syncthreads();
    if (threadIdx.x == 0) g_mask_is_u8 = (cnt > 0) ? 1 : 0;
}

__global__ void mask_convert_kernel(const unsigned char* __restrict__ m) {
    const int u8 = g_mask_is_u8;
    size_t i = (size_t)blockIdx.x * blockDim.x + threadIdx.x;
    if (i < MASK_N_) {
        if (u8) g_mask[i] = (__ldg(&m[i]) != 0);
        else    g_mask[i] = (__ldg(&((const int*)m)[i]) != 0);
    }
}

// ---------------- tf32 tensor-core GEMM: C[8192,512] = A @ B (+resid) ---------
// block tile 128x128, K=512, 8 warps of 64x32 warp tiles
__global__ __launch_bounds__(256)
void gemm_tc(const float* __restrict__ A, const float* __restrict__ Bm,
             const float* __restrict__ R, float* __restrict__ C, int addResid)
{
    __shared__ uint32_t As[128 * 36];   // [m][k] tf32, pad 36 -> frag loads conflict-free
    __shared__ uint32_t Bs[32 * 132];   // [k][n] tf32, pad 132 -> frag loads 2-way
    const int t = threadIdx.x;
    const int w = t >> 5, lane = t & 31, gid = lane >> 2, tid4 = lane & 3;
    const int wm = w & 1, wn = w >> 1;
    const int brow = blockIdx.y * 128, bcol = blockIdx.x * 128;

    float acc[4][4][4];
    #pragma unroll
    for (int mt = 0; mt < 4; mt++)
        #pragma unroll
        for (int nt = 0; nt < 4; nt++)
            #pragma unroll
            for (int i = 0; i < 4; i++) acc[mt][nt][i] = 0.f;

    for (int k0 = 0; k0 < 512; k0 += 32) {
        __syncthreads();
        #pragma unroll
        for (int i = 0; i < 4; i++) {
            int idx = i * 256 + t;
            int m  = idx >> 3, k4 = (idx & 7) * 4;
            float4 v = *(const float4*)&A[(size_t)(brow + m) * 512 + k0 + k4];
            uint4 u = make_uint4(f2tf(v.x), f2tf(v.y), f2tf(v.z), f2tf(v.w));
            *(uint4*)&As[m * 36 + k4] = u;
            int kr = idx >> 5, nc = (idx & 31) * 4;
            float4 bv = *(const float4*)&Bm[(size_t)(k0 + kr) * 512 + bcol + nc];
            uint4 ub = make_uint4(f2tf(bv.x), f2tf(bv.y), f2tf(bv.z), f2tf(bv.w));
            *(uint4*)&Bs[kr * 132 + nc] = ub;
        }
        __syncthreads();
        #pragma unroll
        for (int kk = 0; kk < 4; kk++) {
            const int kb = kk * 8;
            uint32_t af[4][4];
            #pragma unroll
            for (int mt = 0; mt < 4; mt++) {
                int row = wm * 64 + mt * 16 + gid;
                af[mt][0] = As[row * 36 + kb + tid4];
                af[mt][1] = As[(row + 8) * 36 + kb + tid4];
                af[mt][2] = As[row * 36 + kb + tid4 + 4];
                af[mt][3] = As[(row + 8) * 36 + kb + tid4 + 4];
            }
            uint32_t bf[4][2];
            #pragma unroll
            for (int nt = 0; nt < 4; nt++) {
                int n = wn * 32 + nt * 8 + gid;
                bf[nt][0] = Bs[(kb + tid4) * 132 + n];
                bf[nt][1] = Bs[(kb + tid4 + 4) * 132 + n];
            }
            #pragma unroll
            for (int mt = 0; mt < 4; mt++)
                #pragma unroll
                for (int nt = 0; nt < 4; nt++)
                    mma8(acc[mt][nt], af[mt], bf[nt][0], bf[nt][1]);
        }
    }

    #pragma unroll
    for (int mt = 0; mt < 4; mt++) {
        #pragma unroll
        for (int nt = 0; nt < 4; nt++) {
            size_t row = (size_t)(brow + wm * 64 + mt * 16 + gid);
            size_t col = (size_t)(bcol + wn * 32 + nt * 8 + 2 * tid4);
            float2 v0 = make_float2(acc[mt][nt][0], acc[mt][nt][1]);
            float2 v1 = make_float2(acc[mt][nt][2], acc[mt][nt][3]);
            if (addResid) {
                float2 r0 = *(const float2*)&R[row * 512 + col];
                float2 r1 = *(const float2*)&R[(row + 8) * 512 + col];
                v0.x += r0.x; v0.y += r0.y; v1.x += r1.x; v1.y += r1.y;
            }
            *(float2*)&C[row * 512 + col] = v0;
            *(float2*)&C[(row + 8) * 512 + col] = v1;
        }
    }
}

// ---------------- fused attention (tf32 mma): scores -> softmax -> attn -> ctx
// block = (b, h, 32 q rows), 256 threads (8 warps)
// dynamic smem: sS[32][1028] f32 + sKV[128][68] tf32 + sQ[32][68] tf32 = 175104 B
__global__ __launch_bounds__(256)
void attn_kernel(const float* __restrict__ Q, const float* __restrict__ K,
                 const float* __restrict__ V,
                 float* __restrict__ attn, float* __restrict__ ctx)
{
    extern __shared__ float sm[];
    float*    sS  = sm;                               // 32*1028 fp32 scores
    uint32_t* sKV = (uint32_t*)(sm + 32 * SP);        // 128*68 tf32
    uint32_t* sQ  = sKV + 128 * 68;                   // 32*68 tf32

    const int t = threadIdx.x;
    const int w = t >> 5, lane = t & 31, gid = lane >> 2, tid4 = lane & 3;
    const int b = blockIdx.z, h = blockIdx.y;
    const int q0 = blockIdx.x * 32;
    const size_t rowbase = (size_t)b * 1024;
    const float* Qb = Q + (rowbase + q0) * 512 + h * 64;
    const float* Kb = K + rowbase * 512 + h * 64;
    const float* Vb = V + rowbase * 512 + h * 64;

    // load Q tile 32x64 -> tf32
    #pragma unroll
    for (int p = 0; p < 2; p++) {
        int idx = p * 256 + t;
        int r = idx >> 4, j = (idx & 15) * 4;
        float4 v = *(const float4*)&Qb[(size_t)r * 512 + j];
        uint4 u = make_uint4(f2tf(v.x), f2tf(v.y), f2tf(v.z), f2tf(v.w));
        *(uint4*)&sQ[r * 68 + j] = u;
    }

    const int wm = w & 1;   // m-half (16 rows)
    const int wn = w >> 1;  // n-quarter

    // ---- Phase 1: raw scores via mma into sS ----
    for (int ch = 0; ch < 8; ch++) {
        const int s0 = ch * 128;
        __syncthreads();
        #pragma unroll
        for (int p = 0; p < 8; p++) {
            int idx = p * 256 + t;
            int r = idx >> 4, j = (idx & 15) * 4;
            float4 v = *(const float4*)&Kb[(size_t)(s0 + r) * 512 + j];
            uint4 u = make_uint4(f2tf(v.x), f2tf(v.y), f2tf(v.z), f2tf(v.w));
            *(uint4*)&sKV[r * 68 + j] = u;
        }
        __syncthreads();
        float acc[4][4];
        #pragma unroll
        for (int nt = 0; nt < 4; nt++)
            #pragma unroll
            for (int i = 0; i < 4; i++) acc[nt][i] = 0.f;
        #pragma unroll
        for (int ks = 0; ks < 8; ks++) {
            const int k0 = ks * 8;
            uint32_t af[4];
            int arow = wm * 16 + gid;
            af[0] = sQ[arow * 68 + k0 + tid4];
            af[1] = sQ[(arow + 8) * 68 + k0 + tid4];
            af[2] = sQ[arow * 68 + k0 + tid4 + 4];
            af[3] = sQ[(arow + 8) * 68 + k0 + tid4 + 4];
            #pragma unroll
            for (int nt = 0; nt < 4; nt++) {
                int n = wn * 32 + nt * 8 + gid;
                uint32_t b0 = sKV[n * 68 + k0 + tid4];
                uint32_t b1 = sKV[n * 68 + k0 + tid4 + 4];
                mma8(acc[nt], af, b0, b1);
            }
        }
        #pragma unroll
        for (int nt = 0; nt < 4; nt++) {
            int row = wm * 16 + gid;
            int col = s0 + wn * 32 + nt * 8 + 2 * tid4;
            *(float2*)&sS[row * SP + col]       = make_float2(acc[nt][0], acc[nt][1]);
            *(float2*)&sS[(row + 8) * SP + col] = make_float2(acc[nt][2], acc[nt][3]);
        }
    }
    __syncthreads();

    // ---- Phase 2: mask + scale + exact softmax; write attn ----
    {
        const unsigned char* mb = g_mask + ((size_t)b * 1024 + q0) * 1024;
        #pragma unroll
        for (int ri = 0; ri < 4; ri++) {
            int r = w * 4 + ri;
            float* srow = &sS[r * SP];
            const uchar4* mrow = (const uchar4*)(mb + (size_t)r * 1024);
            float mx = -3.0e38f;
            #pragma unroll
            for (int j = 0; j < 8; j++) {
                int c4 = lane + j * 32;
                uchar4 mk = mrow[c4];
                float4 sv = *(float4*)&srow[c4 * 4];
                sv.x = mk.x ? -1e9f : sv.x * 0.125f;
                sv.y = mk.y ? -1e9f : sv.y * 0.125f;
                sv.z = mk.z ? -1e9f : sv.z * 0.125f;
                sv.w = mk.w ? -1e9f : sv.w * 0.125f;
                *(float4*)&srow[c4 * 4] = sv;
                mx = fmaxf(mx, fmaxf(fmaxf(sv.x, sv.y), fmaxf(sv.z, sv.w)));
            }
            #pragma unroll
            for (int o = 16; o > 0; o >>= 1)
                mx = fmaxf(mx, __shfl_xor_sync(0xffffffffu, mx, o));
            float l = 0.f;
            #pragma unroll
            for (int j = 0; j < 8; j++) {
                int c4 = lane + j * 32;
                float4 sv = *(float4*)&srow[c4 * 4];
                sv.x = __expf(sv.x - mx);
                sv.y = __expf(sv.y - mx);
                sv.z = __expf(sv.z - mx);
                sv.w = __expf(sv.w - mx);
                *(float4*)&srow[c4 * 4] = sv;
                l += (sv.x + sv.y) + (sv.z + sv.w);
            }
            #pragma unroll
            for (int o = 16; o > 0; o >>= 1)
                l += __shfl_xor_sync(0xffffffffu, l, o);
            float rinv = 1.0f / l;
            float* arow = attn + ((size_t)(b * 8 + h) * 1024 + q0 + r) * 1024;
            #pragma unroll
            for (int j = 0; j < 8; j++) {
                int c4 = lane + j * 32;
                float4 sv = *(float4*)&srow[c4 * 4];
                sv.x *= rinv; sv.y *= rinv; sv.z *= rinv; sv.w *= rinv;
                *(float4*)&srow[c4 * 4] = sv;
                *(float4*)&arow[c4 * 4] = sv;
            }
        }
    }

    // ---- Phase 3: ctx = P @ V via mma (warp = 16 rows x 16 cols) ----
    float acc2[2][4];
    #pragma unroll
    for (int nt = 0; nt < 2; nt++)
        #pragma unroll
        for (int i = 0; i < 4; i++) acc2[nt][i] = 0.f;

    for (int ch = 0; ch < 8; ch++) {
        const int s0 = ch * 128;
        __syncthreads();
        #pragma unroll
        for (int p = 0; p < 8; p++) {
            int idx = p * 256 + t;
            int r = idx >> 4, j = (idx & 15) * 4;
            float4 v = *(const float4*)&Vb[(size_t)(s0 + r) * 512 + j];
            uint4 u = make_uint4(f2tf(v.x), f2tf(v.y), f2tf(v.z), f2tf(v.w));
            *(uint4*)&sKV[r * 68 + j] = u;
        }
        __syncthreads();
        #pragma unroll
        for (int ks = 0; ks < 16; ks++) {
            const int kc = s0 + ks * 8;   // column in sS (kv position)
            const int kl = ks * 8;        // row in sKV (local)
            int arow = wm * 16 + gid;
            uint32_t af[4];
            af[0] = f2tf(sS[arow * SP + kc + tid4]);
            af[1] = f2tf(sS[(arow + 8) * SP + kc + tid4]);
            af[2] = f2tf(sS[arow * SP + kc + tid4 + 4]);
            af[3] = f2tf(sS[(arow + 8) * SP + kc + tid4 + 4]);
            #pragma unroll
            for (int nt = 0; nt < 2; nt++) {
                int n = wn * 16 + nt * 8 + gid;
                uint32_t b0 = sKV[(kl + tid4) * 68 + n];
                uint32_t b1 = sKV[(kl + tid4 + 4) * 68 + n];
                mma8(acc2[nt], af, b0, b1);
            }
        }
    }
    // write ctx (each warp owns distinct 16x16 tile)
    {
        float* cb = ctx + (rowbase + q0) * 512 + h * 64;
        #pragma unroll
        for (int nt = 0; nt < 2; nt++) {
            int row = wm * 16 + gid;
            int col = wn * 16 + nt * 8 + 2 * tid4;
            *(float2*)&cb[(size_t)row * 512 + col]       = make_float2(acc2[nt][0], acc2[nt][1]);
            *(float2*)&cb[(size_t)(row + 8) * 512 + col] = make_float2(acc2[nt][2], acc2[nt][3]);
        }
    }
}

// ---------------- LayerNorm over last dim (512), one row per block -----------
__global__ __launch_bounds__(128)
void ln_kernel(const float* __restrict__ X, const float* __restrict__ gamma,
               const float* __restrict__ beta, float* __restrict__ out)
{
    __shared__ float red[8];
    const int row = blockIdx.x, t = threadIdx.x;
    const float* x = X + (size_t)row * 512;
    float4 v = *(const float4*)&x[t * 4];
    float s  = (v.x + v.y) + (v.z + v.w);
    float s2 = v.x * v.x + v.y * v.y + v.z * v.z + v.w * v.w;
    #pragma unroll
    for (int o = 16; o > 0; o >>= 1) {
        s  += __shfl_xor_sync(0xffffffffu, s,  o);
        s2 += __shfl_xor_sync(0xffffffffu, s2, o);
    }
    const int warp = t >> 5, lane = t & 31;
    if (lane == 0) { red[warp] = s; red[4 + warp] = s2; }
    __syncthreads();
    s  = red[0] + red[1] + red[2] + red[3];
    s2 = red[4] + red[5] + red[6] + red[7];
    float mean = s * (1.0f / 512.0f);
    float var  = s2 * (1.0f / 512.0f) - mean * mean;
    float rstd = rsqrtf(var + 1e-5f);
    float4 gv = *(const float4*)&gamma[t * 4];
    float4 bv = *(const float4*)&beta[t * 4];
    float4 o4;
    o4.x = (v.x - mean) * rstd * gv.x + bv.x;
    o4.y = (v.y - mean) * rstd * gv.y + bv.y;
    o4.z = (v.z - mean) * rstd * gv.z + bv.z;
    o4.w = (v.w - mean) * rstd * gv.w + bv.w;
    *(float4*)&out[(size_t)row * 512 + t * 4] = o4;
}

// ---------------- launch ------------------------------------------------------
extern "C" void kernel_launch(void* const* d_in, const int* in_sizes, int n_in,
                              void* d_out, int out_size)
{
    const float* iQ   = (const float*)d_in[0];
    const float* iK   = (const float*)d_in[1];
    const float* iV   = (const float*)d_in[2];
    const unsigned char* maskRaw = (const unsigned char*)d_in[3];
    const float* WQ   = (const float*)d_in[4];
    const float* WK   = (const float*)d_in[5];
    const float* WV   = (const float*)d_in[6];
    const float* Wfc  = (const float*)d_in[7];
    const float* gam  = (const float*)d_in[8];
    const float* bet  = (const float*)d_in[9];

    float *gq, *gk, *gv, *gctx, *gpre, *gattn;
    cudaGetSymbolAddress((void**)&gq,    g_Q);
    cudaGetSymbolAddress((void**)&gk,    g_K);
    cudaGetSymbolAddress((void**)&gv,    g_V);
    cudaGetSymbolAddress((void**)&gctx,  g_ctx);
    cudaGetSymbolAddress((void**)&gpre,  g_pre);
    cudaGetSymbolAddress((void**)&gattn, g_attn_scratch);

    float* out = (float*)d_out;
    float* out_ln;
    float* out_attn;
    size_t os = (size_t)out_size;
    if (os >= LN_N_ + ATTN_N_)      { out_ln = out;   out_attn = out + LN_N_; }
    else if (os == ATTN_N_)         { out_attn = out; out_ln = gq; }
    else                            { out_ln = out;   out_attn = gattn; }

    // mask normalization (dtype-robust)
    mask_detect_kernel<<<1, 256>>>(maskRaw);
    mask_convert_kernel<<<(int)((MASK_N_ + 255) / 256), 256>>>(maskRaw);

    // QKV projections (tf32 tensor cores)
    dim3 gGemm(4, 64);
    gemm_tc<<<gGemm, 256>>>(iQ, WQ, nullptr, gq, 0);
    gemm_tc<<<gGemm, 256>>>(iK, WK, nullptr, gk, 0);
    gemm_tc<<<gGemm, 256>>>(iV, WV, nullptr, gv, 0);

    // fused attention
    const int smemBytes = (32 * SP + 128 * 68 + 32 * 68) * 4;  // 175104
    cudaFuncSetAttribute(attn_kernel, cudaFuncAttributeMaxDynamicSharedMemorySize, smemBytes);
    attn_kernel<<<dim3(32, 8, 8), 256, smemBytes>>>(gq, gk, gv, out_attn, gctx);

    // output projection + residual (tf32 tensor cores)
    gemm_tc<<<gGemm, 256>>>(gctx, Wfc, iQ, gpre, 1);

    // layernorm
    ln_kernel<<<8192, 128>>>(gpre, gam, bet, out_ln);
}